// round 1
// baseline (speedup 1.0000x reference)
#include <cuda_runtime.h>
#include <cuda_fp16.h>

// Problem constants (fixed shapes from reference)
#define M_DIM 8192      // B*S
#define N_DIM 4096
#define K_DIM 4096
#define NOUT  128
#define KE    4224      // K_DIM + NOUT (outlier GEMM fused as extra K)

// Scratch: fp16 operand matrices (device globals — no runtime allocation)
__device__ __align__(128) __half g_Xe[(size_t)M_DIM * KE]; // [M, KE] row-major
__device__ __align__(128) __half g_We[(size_t)N_DIM * KE]; // [N, KE] row-major

// ---------------------------------------------------------------------------
// Prep 1: x fp32 -> fp16, with the last 128 features duplicated at k=4096..4223
// ---------------------------------------------------------------------------
__global__ void prep_x(const float* __restrict__ x) {
    const int per_row = KE / 4; // 1056 float4-groups per row
    int idx = blockIdx.x * blockDim.x + threadIdx.x;
    if (idx >= M_DIM * per_row) return;
    int m  = idx / per_row;
    int k4 = (idx - m * per_row) * 4;
    // k4 < 4096: normal columns; k4 >= 4096: outlier re-read of x[:, k4-128]
    const float* src = x + (size_t)m * K_DIM + (k4 < K_DIM ? k4 : k4 - NOUT);
    float4 v = *(const float4*)src;
    __half2* dst = (__half2*)(g_Xe + (size_t)m * KE + k4);
    dst[0] = __floats2half2_rn(v.x, v.y);
    dst[1] = __floats2half2_rn(v.z, v.w);
}

// ---------------------------------------------------------------------------
// Prep 2: dequantize W = q*s+z -> fp16; append oweight at k=4096..4223
// ---------------------------------------------------------------------------
__global__ void prep_w(const int* __restrict__ qw,
                       const float* __restrict__ scales,
                       const float* __restrict__ zeros,
                       const float* __restrict__ ow) {
    const int per_row = KE / 4;
    int idx = blockIdx.x * blockDim.x + threadIdx.x;
    if (idx >= N_DIM * per_row) return;
    int n  = idx / per_row;
    int k4 = (idx - n * per_row) * 4;
    __half2 h0, h1;
    if (k4 < K_DIM) {
        int4 q = *(const int4*)(qw + (size_t)n * K_DIM + k4);
        int g = k4 >> 7;                       // group size 128; 4 elems share g
        float s = scales[g * N_DIM + n];
        float z = zeros[g * N_DIM + n];
        h0 = __floats2half2_rn((float)q.x * s + z, (float)q.y * s + z);
        h1 = __floats2half2_rn((float)q.z * s + z, (float)q.w * s + z);
    } else {
        float4 o = *(const float4*)(ow + (size_t)n * NOUT + (k4 - K_DIM));
        h0 = __floats2half2_rn(o.x, o.y);
        h1 = __floats2half2_rn(o.z, o.w);
    }
    __half2* dst = (__half2*)(g_We + (size_t)n * KE + k4);
    dst[0] = h0; dst[1] = h1;
}

// ---------------------------------------------------------------------------
// GEMM: y[M,N] = Xe @ We^T + bias, fp16 inputs, fp32 accumulate.
// CTA tile 128x128, K-step 32, 3-stage cp.async pipeline, 8 warps (2x4),
// warp tile 64x32, mma.sync m16n8k16. XOR swizzle on 16B chunks for
// conflict-free ldmatrix and cp.async stores.
// ---------------------------------------------------------------------------
__global__ __launch_bounds__(256, 2) void gemm_f16(const float* __restrict__ bias,
                                                   float* __restrict__ y) {
    __shared__ __align__(16) __half As[3][128 * 32];
    __shared__ __align__(16) __half Bs[3][128 * 32];

    const int t    = threadIdx.x;
    const int lane = t & 31;
    const int w    = t >> 5;
    const int bm   = blockIdx.y << 7;
    const int bn   = blockIdx.x << 7;
    const int wm   = (w >> 2) << 6;  // 0 or 64
    const int wn   = (w & 3) << 5;   // 0,32,64,96

    const __half* Ag = g_Xe + (size_t)bm * KE;
    const __half* Bg = g_We + (size_t)bn * KE;

    // loader coords: each thread cp.asyncs one 16B chunk of 2 rows per matrix
    const int lr = t >> 2;  // row 0..63 (and +64)
    const int lc = t & 3;   // logical 8-half chunk within the 32-wide k-step

    float acc[4][4][4];
#pragma unroll
    for (int i = 0; i < 4; i++)
#pragma unroll
        for (int j = 0; j < 4; j++)
#pragma unroll
            for (int r = 0; r < 4; r++) acc[i][j][r] = 0.f;

    unsigned sA = (unsigned)__cvta_generic_to_shared(As);
    unsigned sB = (unsigned)__cvta_generic_to_shared(Bs);

    // swizzled half-index within one 128x32 tile
    auto swz = [](int row, int chunk) {
        return (row << 5) + ((chunk ^ ((row >> 1) & 3)) << 3);
    };

    auto load_stage = [&](int buf, int ks) {
        int k0 = ks << 5;
#pragma unroll
        for (int i = 0; i < 2; i++) {
            int row = lr + (i << 6);
            unsigned da = sA + (unsigned)((buf * 4096 + swz(row, lc)) << 1);
            const __half* ga = Ag + (size_t)row * KE + k0 + (lc << 3);
            asm volatile("cp.async.cg.shared.global [%0], [%1], 16;\n" ::"r"(da), "l"(ga));
            unsigned db = sB + (unsigned)((buf * 4096 + swz(row, lc)) << 1);
            const __half* gb = Bg + (size_t)row * KE + k0 + (lc << 3);
            asm volatile("cp.async.cg.shared.global [%0], [%1], 16;\n" ::"r"(db), "l"(gb));
        }
    };

    const int NSTEP = KE / 32;  // 132
    load_stage(0, 0);
    asm volatile("cp.async.commit_group;\n");
    load_stage(1, 1);
    asm volatile("cp.async.commit_group;\n");

    // ldmatrix lane addressing (non-trans for both A and B since both are K-major)
    const int a_row  = wm + (lane & 15);
    const int a_cofs = lane >> 4;                         // 0/1 -> k+0 / k+8
    const int b_row  = wn + (lane & 7) + ((lane >> 4) << 3);
    const int b_cofs = (lane >> 3) & 1;

    for (int ks = 0; ks < NSTEP; ks++) {
        asm volatile("cp.async.wait_group 1;\n");
        __syncthreads();
        int buf = ks % 3;
        if (ks + 2 < NSTEP) load_stage((ks + 2) % 3, ks + 2);
        asm volatile("cp.async.commit_group;\n");

        unsigned baseA = sA + (unsigned)(buf * 8192);
        unsigned baseB = sB + (unsigned)(buf * 8192);

#pragma unroll
        for (int p = 0; p < 2; p++) {  // two k16 phases per 32-wide step
            unsigned a[4][4];
#pragma unroll
            for (int i = 0; i < 4; i++) {
                int row = a_row + (i << 4);
                int chunk = (p << 1) + a_cofs;
                unsigned addr = baseA + (unsigned)(swz(row, chunk) << 1);
                asm volatile(
                    "ldmatrix.sync.aligned.m8n8.x4.shared.b16 {%0,%1,%2,%3}, [%4];\n"
                    : "=r"(a[i][0]), "=r"(a[i][1]), "=r"(a[i][2]), "=r"(a[i][3])
                    : "r"(addr));
            }
            unsigned b[4][2];
#pragma unroll
            for (int jj = 0; jj < 2; jj++) {
                int row = b_row + (jj << 4);
                int chunk = (p << 1) + b_cofs;
                unsigned addr = baseB + (unsigned)(swz(row, chunk) << 1);
                unsigned r0, r1, r2, r3;
                asm volatile(
                    "ldmatrix.sync.aligned.m8n8.x4.shared.b16 {%0,%1,%2,%3}, [%4];\n"
                    : "=r"(r0), "=r"(r1), "=r"(r2), "=r"(r3)
                    : "r"(addr));
                b[jj * 2][0] = r0; b[jj * 2][1] = r1;
                b[jj * 2 + 1][0] = r2; b[jj * 2 + 1][1] = r3;
            }
#pragma unroll
            for (int i = 0; i < 4; i++)
#pragma unroll
                for (int j = 0; j < 4; j++)
                    asm volatile(
                        "mma.sync.aligned.m16n8k16.row.col.f32.f16.f16.f32 "
                        "{%0,%1,%2,%3}, {%4,%5,%6,%7}, {%8,%9}, {%0,%1,%2,%3};\n"
                        : "+f"(acc[i][j][0]), "+f"(acc[i][j][1]),
                          "+f"(acc[i][j][2]), "+f"(acc[i][j][3])
                        : "r"(a[i][0]), "r"(a[i][1]), "r"(a[i][2]), "r"(a[i][3]),
                          "r"(b[j][0]), "r"(b[j][1]));
        }
    }

    // epilogue: add bias, write fp32
#pragma unroll
    for (int i = 0; i < 4; i++) {
        int row = bm + wm + (i << 4) + (lane >> 2);
#pragma unroll
        for (int j = 0; j < 4; j++) {
            int col = bn + wn + (j << 3) + ((lane & 3) << 1);
            float2 bb = *(const float2*)(bias + col);
            float2 o0 = make_float2(acc[i][j][0] + bb.x, acc[i][j][1] + bb.y);
            float2 o1 = make_float2(acc[i][j][2] + bb.x, acc[i][j][3] + bb.y);
            *(float2*)(y + (size_t)row * N_DIM + col)       = o0;
            *(float2*)(y + (size_t)(row + 8) * N_DIM + col) = o1;
        }
    }
}

// ---------------------------------------------------------------------------
extern "C" void kernel_launch(void* const* d_in, const int* in_sizes, int n_in,
                              void* d_out, int out_size) {
    const float* x      = (const float*)d_in[0];
    const int*   qw     = (const int*)d_in[1];
    const float* scales = (const float*)d_in[2];
    const float* zeros  = (const float*)d_in[3];
    const float* ow     = (const float*)d_in[4];
    const float* bias   = (const float*)d_in[5];
    float*       y      = (float*)d_out;

    prep_x<<<(M_DIM * (KE / 4)) / 256, 256>>>(x);
    prep_w<<<(N_DIM * (KE / 4)) / 256, 256>>>(qw, scales, zeros, ow);

    dim3 grid(N_DIM / 128, M_DIM / 128);  // (32, 64)
    gemm_f16<<<grid, 256>>>(bias, y);
}

// round 3
// speedup vs baseline: 2.7977x; 2.7977x over previous
#include <cuda_runtime.h>
#include <cuda_fp16.h>
#include <cstdint>

// ===========================================================================
// Arch-feature detection: tcgen05 only exists on 'a'/'f' feature targets.
// The harness may run a ptxas pass with .target sm_103 (no 'a'); that pass
// must not see any tcgen05 PTX or the whole build aborts.
// ===========================================================================
#define HAS_TCGEN05 0
#if defined(__CUDA_ARCH__) && (__CUDA_ARCH__ >= 1000)
#  if defined(__CUDA_ARCH_FAMILY_SPECIFIC__) || defined(__CUDA_ARCH_SPECIFIC__)
#    undef HAS_TCGEN05
#    define HAS_TCGEN05 1
#  elif defined(__CUDA_ARCH_HAS_FEATURE__)
#    if __CUDA_ARCH_HAS_FEATURE__(SM103_ALL) || __CUDA_ARCH_HAS_FEATURE__(SM100_ALL)
#      undef HAS_TCGEN05
#      define HAS_TCGEN05 1
#    endif
#  endif
#endif

// Problem constants
#define M_DIM 8192
#define N_DIM 4096
#define K_DIM 4096
#define NOUT  128
#define KE    4224            // K + NOUT (outlier GEMM fused as extra K)

// tcgen05 GEMM tiling
#define TM 128
#define TN 256
#define CH_K 64
#define NCHUNK (KE / CH_K)    // 66
#define NSTAGE 4
#define A_STG_BYTES (TM * 128)
#define B_STG_BYTES (TN * 128)
#define STG_BYTES   (A_STG_BYTES + B_STG_BYTES)   // 49152
#define CTRL_OFF    (NSTAGE * STG_BYTES)          // 196608
#define SMEM_TOTAL  (CTRL_OFF + 64)

#define IDESC ((1u << 4) | ((TN / 8) << 17) | ((TM / 16) << 24))
#define DESC_BASE ((uint64_t(2) << 61) | (uint64_t(1) << 46) | (uint64_t(64) << 32) | (uint64_t(1) << 16))

// Scratch fp16 operands (device globals — no runtime allocation)
__device__ __align__(128) __half g_Xe[(size_t)M_DIM * KE];
__device__ __align__(128) __half g_We[(size_t)N_DIM * KE];

// ---------------------------------------------------------------------------
// Prep kernels (fp32 -> fp16, dequant, outlier fusion) — arch-agnostic
// ---------------------------------------------------------------------------
__global__ void prep_x(const float* __restrict__ x) {
    const int per_row = KE / 4;
    int idx = blockIdx.x * blockDim.x + threadIdx.x;
    if (idx >= M_DIM * per_row) return;
    int m  = idx / per_row;
    int k4 = (idx - m * per_row) * 4;
    const float* src = x + (size_t)m * K_DIM + (k4 < K_DIM ? k4 : k4 - NOUT);
    float4 v = *(const float4*)src;
    __half2* dst = (__half2*)(g_Xe + (size_t)m * KE + k4);
    dst[0] = __floats2half2_rn(v.x, v.y);
    dst[1] = __floats2half2_rn(v.z, v.w);
}

__global__ void prep_w(const int* __restrict__ qw,
                       const float* __restrict__ scales,
                       const float* __restrict__ zeros,
                       const float* __restrict__ ow) {
    const int per_row = KE / 4;
    int idx = blockIdx.x * blockDim.x + threadIdx.x;
    if (idx >= N_DIM * per_row) return;
    int n  = idx / per_row;
    int k4 = (idx - n * per_row) * 4;
    __half2 h0, h1;
    if (k4 < K_DIM) {
        int4 q = *(const int4*)(qw + (size_t)n * K_DIM + k4);
        int g = k4 >> 7;
        float s = scales[g * N_DIM + n];
        float z = zeros[g * N_DIM + n];
        h0 = __floats2half2_rn((float)q.x * s + z, (float)q.y * s + z);
        h1 = __floats2half2_rn((float)q.z * s + z, (float)q.w * s + z);
    } else {
        float4 o = *(const float4*)(ow + (size_t)n * NOUT + (k4 - K_DIM));
        h0 = __floats2half2_rn(o.x, o.y);
        h1 = __floats2half2_rn(o.z, o.w);
    }
    __half2* dst = (__half2*)(g_We + (size_t)n * KE + k4);
    dst[0] = h0; dst[1] = h1;
}

// ===========================================================================
// Path A: tcgen05 GEMM (compiled only on 'a'/'f' feature targets)
// ===========================================================================
#if HAS_TCGEN05
__device__ __forceinline__ uint32_t smem_u32(const void* p) {
    return (uint32_t)__cvta_generic_to_shared(p);
}
__device__ __forceinline__ uint32_t elect_one() {
    uint32_t pred;
    asm volatile("{.reg .pred p; elect.sync _|p, 0xFFFFFFFF; selp.b32 %0, 1, 0, p;}"
                 : "=r"(pred));
    return pred;
}
__device__ __forceinline__ void mma_f16_ss(uint32_t d, uint64_t ad, uint64_t bd,
                                           uint32_t idesc, uint32_t accum) {
    asm volatile(
        "{.reg .pred p; setp.ne.u32 p, %5, 0;\n\t"
        "tcgen05.mma.cta_group::1.kind::f16 [%0], %1, %2, %3, {%4,%4,%4,%4}, p;}\n"
        :: "r"(d), "l"(ad), "l"(bd), "r"(idesc), "r"(0u), "r"(accum) : "memory");
}
__device__ __forceinline__ void mbar_wait(uint32_t addr, uint32_t parity) {
    asm volatile(
        "{.reg .pred P1;\n\t"
        "LAB_WAIT_%=:\n\t"
        "mbarrier.try_wait.parity.acquire.cta.shared::cta.b64 P1, [%0], %1, 0x989680;\n\t"
        "@P1 bra LAB_DONE_%=;\n\t"
        "bra LAB_WAIT_%=;\n\t"
        "LAB_DONE_%=:}\n"
        :: "r"(addr), "r"(parity) : "memory");
}
#endif

extern __shared__ __align__(1024) char smn[];

__global__ void __launch_bounds__(256, 1)
gemm_tc(const float* __restrict__ bias, float* __restrict__ y) {
#if HAS_TCGEN05
    const int tid  = threadIdx.x;
    const int w    = tid >> 5;
    const int lane = tid & 31;
    const int bm   = blockIdx.y * TM;
    const int bn   = blockIdx.x * TN;

    const uint32_t sbase = smem_u32(smn);
    const uint32_t ctrl  = sbase + CTRL_OFF;

    if (w == 0) {
        asm volatile("tcgen05.alloc.cta_group::1.sync.aligned.shared::cta.b32 [%0], %1;"
                     :: "r"(ctrl), "r"((uint32_t)TN) : "memory");
        asm volatile("tcgen05.relinquish_alloc_permit.cta_group::1.sync.aligned;");
    }
    if (tid == 0) {
#pragma unroll
        for (int b = 0; b < NSTAGE; b++)
            asm volatile("mbarrier.init.shared.b64 [%0], 1;" :: "r"(ctrl + 8 + 8 * b) : "memory");
    }
    __syncthreads();
    uint32_t tmem;
    asm volatile("ld.shared.b32 %0, [%1];" : "=r"(tmem) : "r"(ctrl));

    const __half* Ag = g_Xe + (size_t)bm * KE;
    const __half* Bg = g_We + (size_t)bn * KE;

    auto load = [&](int b, int c) {
        const int k0 = c * CH_K;
        const uint32_t aB = sbase + b * STG_BYTES;
        const uint32_t bB = aB + A_STG_BYTES;
#pragma unroll
        for (int i = 0; i < 4; i++) {
            int idx = tid + i * 256;
            int row = idx >> 3, cc = idx & 7;
            uint32_t dst = aB + (uint32_t)(row * 128 + ((cc ^ (row & 7)) << 4));
            const __half* src = Ag + (size_t)row * KE + k0 + cc * 8;
            asm volatile("cp.async.cg.shared.global [%0], [%1], 16;" :: "r"(dst), "l"(src));
        }
#pragma unroll
        for (int i = 0; i < 8; i++) {
            int idx = tid + i * 256;
            int row = idx >> 3, cc = idx & 7;
            uint32_t dst = bB + (uint32_t)(row * 128 + ((cc ^ (row & 7)) << 4));
            const __half* src = Bg + (size_t)row * KE + k0 + cc * 8;
            asm volatile("cp.async.cg.shared.global [%0], [%1], 16;" :: "r"(dst), "l"(src));
        }
    };

#pragma unroll
    for (int c = 0; c < 3; c++) {
        load(c, c);
        asm volatile("cp.async.commit_group;");
    }

    for (int ks = 0; ks < NCHUNK; ks++) {
        asm volatile("cp.async.wait_group 2;");
        __syncthreads();

        const int buf = ks & 3;
        if (w == 0) {
            asm volatile("fence.proxy.async.shared::cta;" ::: "memory");
            asm volatile("tcgen05.fence::after_thread_sync;" ::: "memory");
            if (elect_one()) {
                const uint32_t aAddr = sbase + buf * STG_BYTES;
                const uint64_t ad = DESC_BASE | ((aAddr >> 4) & 0x3FFF);
                const uint64_t bd = DESC_BASE | (((aAddr + A_STG_BYTES) >> 4) & 0x3FFF);
#pragma unroll
                for (int kk = 0; kk < 4; kk++)
                    mma_f16_ss(tmem, ad + kk * 2, bd + kk * 2, IDESC,
                               (ks > 0 || kk > 0) ? 1u : 0u);
                asm volatile(
                    "tcgen05.commit.cta_group::1.mbarrier::arrive::one.shared::cluster.b64 [%0];"
                    :: "r"(ctrl + 8 + 8 * buf) : "memory");
            }
        }

        if (ks + 3 < NCHUNK) {
            const int nb = (ks + 3) & 3;
            if (ks > 0)
                mbar_wait(ctrl + 8 + 8 * nb, ((uint32_t)(ks - 1) >> 2) & 1u);
            load(nb, ks + 3);
        }
        asm volatile("cp.async.commit_group;");
    }

    {
        const int lastc = NCHUNK - 1;
        mbar_wait(ctrl + 8 + 8 * (lastc & 3), ((uint32_t)lastc >> 2) & 1u);
    }
    asm volatile("tcgen05.fence::after_thread_sync;" ::: "memory");

    {
        const uint32_t warp_off = (uint32_t)((tid & 127) >> 5) << 21;
        const int colBase = (w >> 2) << 7;
        const int m = bm + ((w & 3) << 5) + lane;
        float* yrow = y + (size_t)m * N_DIM;
#pragma unroll
        for (int cb = 0; cb < 128; cb += 32) {
            uint32_t r[32];
            asm volatile(
                "tcgen05.ld.sync.aligned.32x32b.x32.b32 "
                "{%0,%1,%2,%3,%4,%5,%6,%7,%8,%9,%10,%11,%12,%13,%14,%15,"
                "%16,%17,%18,%19,%20,%21,%22,%23,%24,%25,%26,%27,%28,%29,%30,%31}, [%32];"
                : "=r"(r[0]), "=r"(r[1]), "=r"(r[2]), "=r"(r[3]), "=r"(r[4]), "=r"(r[5]),
                  "=r"(r[6]), "=r"(r[7]), "=r"(r[8]), "=r"(r[9]), "=r"(r[10]), "=r"(r[11]),
                  "=r"(r[12]), "=r"(r[13]), "=r"(r[14]), "=r"(r[15]), "=r"(r[16]), "=r"(r[17]),
                  "=r"(r[18]), "=r"(r[19]), "=r"(r[20]), "=r"(r[21]), "=r"(r[22]), "=r"(r[23]),
                  "=r"(r[24]), "=r"(r[25]), "=r"(r[26]), "=r"(r[27]), "=r"(r[28]), "=r"(r[29]),
                  "=r"(r[30]), "=r"(r[31])
                : "r"(tmem + (uint32_t)(colBase + cb) + warp_off));
            asm volatile("tcgen05.wait::ld.sync.aligned;" ::: "memory");
            const int col0 = bn + colBase + cb;
#pragma unroll
            for (int q = 0; q < 8; q++) {
                float4 bv = *(const float4*)(bias + col0 + q * 4);
                float4 o;
                o.x = __uint_as_float(r[q * 4 + 0]) + bv.x;
                o.y = __uint_as_float(r[q * 4 + 1]) + bv.y;
                o.z = __uint_as_float(r[q * 4 + 2]) + bv.z;
                o.w = __uint_as_float(r[q * 4 + 3]) + bv.w;
                *(float4*)(yrow + col0 + q * 4) = o;
            }
        }
    }

    __syncthreads();
    if (w == 0) {
        asm volatile("tcgen05.dealloc.cta_group::1.sync.aligned.b32 %0, %1;"
                     :: "r"(tmem), "r"((uint32_t)TN));
    }
#endif  // HAS_TCGEN05
}

// ===========================================================================
// Path B: proven mma.sync fallback (compiled only when tcgen05 is unavailable)
// ===========================================================================
__global__ __launch_bounds__(256, 2) void gemm_f16(const float* __restrict__ bias,
                                                   float* __restrict__ y) {
#if !HAS_TCGEN05
    __shared__ __align__(16) __half As[3][128 * 32];
    __shared__ __align__(16) __half Bs[3][128 * 32];

    const int t    = threadIdx.x;
    const int lane = t & 31;
    const int w    = t >> 5;
    const int bm   = blockIdx.y << 7;
    const int bn   = blockIdx.x << 7;
    const int wm   = (w >> 2) << 6;
    const int wn   = (w & 3) << 5;

    const __half* Ag = g_Xe + (size_t)bm * KE;
    const __half* Bg = g_We + (size_t)bn * KE;

    const int lr = t >> 2;
    const int lc = t & 3;

    float acc[4][4][4];
#pragma unroll
    for (int i = 0; i < 4; i++)
#pragma unroll
        for (int j = 0; j < 4; j++)
#pragma unroll
            for (int r = 0; r < 4; r++) acc[i][j][r] = 0.f;

    unsigned sA = (unsigned)__cvta_generic_to_shared(As);
    unsigned sB = (unsigned)__cvta_generic_to_shared(Bs);

    auto swz = [](int row, int chunk) {
        return (row << 5) + ((chunk ^ ((row >> 1) & 3)) << 3);
    };

    auto load_stage = [&](int buf, int ks) {
        int k0 = ks << 5;
#pragma unroll
        for (int i = 0; i < 2; i++) {
            int row = lr + (i << 6);
            unsigned da = sA + (unsigned)((buf * 4096 + swz(row, lc)) << 1);
            const __half* ga = Ag + (size_t)row * KE + k0 + (lc << 3);
            asm volatile("cp.async.cg.shared.global [%0], [%1], 16;\n" ::"r"(da), "l"(ga));
            unsigned db = sB + (unsigned)((buf * 4096 + swz(row, lc)) << 1);
            const __half* gb = Bg + (size_t)row * KE + k0 + (lc << 3);
            asm volatile("cp.async.cg.shared.global [%0], [%1], 16;\n" ::"r"(db), "l"(gb));
        }
    };

    const int NSTEP = KE / 32;
    load_stage(0, 0);
    asm volatile("cp.async.commit_group;\n");
    load_stage(1, 1);
    asm volatile("cp.async.commit_group;\n");

    const int a_row  = wm + (lane & 15);
    const int a_cofs = lane >> 4;
    const int b_row  = wn + (lane & 7) + ((lane >> 4) << 3);
    const int b_cofs = (lane >> 3) & 1;

    for (int ks = 0; ks < NSTEP; ks++) {
        asm volatile("cp.async.wait_group 1;\n");
        __syncthreads();
        int buf = ks % 3;
        if (ks + 2 < NSTEP) load_stage((ks + 2) % 3, ks + 2);
        asm volatile("cp.async.commit_group;\n");

        unsigned baseA = sA + (unsigned)(buf * 8192);
        unsigned baseB = sB + (unsigned)(buf * 8192);

#pragma unroll
        for (int p = 0; p < 2; p++) {
            unsigned a[4][4];
#pragma unroll
            for (int i = 0; i < 4; i++) {
                int row = a_row + (i << 4);
                int chunk = (p << 1) + a_cofs;
                unsigned addr = baseA + (unsigned)(swz(row, chunk) << 1);
                asm volatile(
                    "ldmatrix.sync.aligned.m8n8.x4.shared.b16 {%0,%1,%2,%3}, [%4];\n"
                    : "=r"(a[i][0]), "=r"(a[i][1]), "=r"(a[i][2]), "=r"(a[i][3])
                    : "r"(addr));
            }
            unsigned b[4][2];
#pragma unroll
            for (int jj = 0; jj < 2; jj++) {
                int row = b_row + (jj << 4);
                int chunk = (p << 1) + b_cofs;
                unsigned addr = baseB + (unsigned)(swz(row, chunk) << 1);
                unsigned r0, r1, r2, r3;
                asm volatile(
                    "ldmatrix.sync.aligned.m8n8.x4.shared.b16 {%0,%1,%2,%3}, [%4];\n"
                    : "=r"(r0), "=r"(r1), "=r"(r2), "=r"(r3)
                    : "r"(addr));
                b[jj * 2][0] = r0; b[jj * 2][1] = r1;
                b[jj * 2 + 1][0] = r2; b[jj * 2 + 1][1] = r3;
            }
#pragma unroll
            for (int i = 0; i < 4; i++)
#pragma unroll
                for (int j = 0; j < 4; j++)
                    asm volatile(
                        "mma.sync.aligned.m16n8k16.row.col.f32.f16.f16.f32 "
                        "{%0,%1,%2,%3}, {%4,%5,%6,%7}, {%8,%9}, {%0,%1,%2,%3};\n"
                        : "+f"(acc[i][j][0]), "+f"(acc[i][j][1]),
                          "+f"(acc[i][j][2]), "+f"(acc[i][j][3])
                        : "r"(a[i][0]), "r"(a[i][1]), "r"(a[i][2]), "r"(a[i][3]),
                          "r"(b[j][0]), "r"(b[j][1]));
        }
    }

#pragma unroll
    for (int i = 0; i < 4; i++) {
        int row = bm + wm + (i << 4) + (lane >> 2);
#pragma unroll
        for (int j = 0; j < 4; j++) {
            int col = bn + wn + (j << 3) + ((lane & 3) << 1);
            float2 bb = *(const float2*)(bias + col);
            float2 o0 = make_float2(acc[i][j][0] + bb.x, acc[i][j][1] + bb.y);
            float2 o1 = make_float2(acc[i][j][2] + bb.x, acc[i][j][3] + bb.y);
            *(float2*)(y + (size_t)row * N_DIM + col)       = o0;
            *(float2*)(y + (size_t)(row + 8) * N_DIM + col) = o1;
        }
    }
#endif  // !HAS_TCGEN05
}

// ---------------------------------------------------------------------------
extern "C" void kernel_launch(void* const* d_in, const int* in_sizes, int n_in,
                              void* d_out, int out_size) {
    const float* x      = (const float*)d_in[0];
    const int*   qw     = (const int*)d_in[1];
    const float* scales = (const float*)d_in[2];
    const float* zeros  = (const float*)d_in[3];
    const float* ow     = (const float*)d_in[4];
    const float* bias   = (const float*)d_in[5];
    float*       y      = (float*)d_out;

    prep_x<<<(M_DIM * (KE / 4)) / 256, 256>>>(x);
    prep_w<<<(N_DIM * (KE / 4)) / 256, 256>>>(qw, scales, zeros, ow);

    // Exactly one of these does work, decided at device-code compile time.
    cudaFuncSetAttribute(gemm_tc, cudaFuncAttributeMaxDynamicSharedMemorySize, SMEM_TOTAL);
    dim3 gridT(N_DIM / TN, M_DIM / TM);   // (16, 64)
    gemm_tc<<<gridT, 256, SMEM_TOTAL>>>(bias, y);

    dim3 gridF(N_DIM / 128, M_DIM / 128); // (32, 64)
    gemm_f16<<<gridF, 256>>>(bias, y);
}